// round 2
// baseline (speedup 1.0000x reference)
#include <cuda_runtime.h>
#include <cuda_bf16.h>
#include <cstdint>

// ---------------------------------------------------------------------------
// Problem constants
// ---------------------------------------------------------------------------
static constexpr long NR   = 32768;   // rows of x
static constexpr int  KD   = 2304;    // C_IN
static constexpr int  NF   = 2816;    // C_WITH_GATE
static constexpr int  SOUT = 2304;    // SIZE_OUT

static constexpr int TM  = 128;       // CTA tile M
static constexpr int TN  = 128;       // CTA tile N
static constexpr int KB  = 64;        // K per stage
static constexpr int NKB = KD / KB;   // 36

static constexpr int TILE_BYTES = 128 * 128;       // one 128x64 bf16 tile = 16KB
static constexpr int STAGE      = 4 * TILE_BYTES;  // Ah Al Bh Bl = 64KB
static constexpr int NSTG       = 3;
static constexpr int SMEM_BYTES = NSTG * STAGE;    // 196608

// ---------------------------------------------------------------------------
// Scratch (device globals; no runtime allocation)
// ---------------------------------------------------------------------------
__device__ __nv_bfloat16 g_xhi[NR * KD];
__device__ __nv_bfloat16 g_xlo[NR * KD];
__device__ __nv_bfloat16 g_whi[(long)NF * KD];   // transposed: [NF, KD]
__device__ __nv_bfloat16 g_wlo[(long)NF * KD];
__device__ float         g_feats[NR * NF];

// ---------------------------------------------------------------------------
// Helpers (baseline compute_103 instructions only: cp.async / ldmatrix / mma)
// ---------------------------------------------------------------------------
__device__ __forceinline__ uint32_t smem_u32(const void* p) {
    uint32_t a;
    asm("{ .reg .u64 t; cvta.to.shared.u64 t, %1; cvt.u32.u64 %0, t; }"
        : "=r"(a) : "l"(p));
    return a;
}

__device__ __forceinline__ uint32_t swz(uint32_t o) {
    return o ^ ((o >> 3) & 0x70);   // SW128 (Swizzle<3,4,3>)
}

__device__ __forceinline__ void cp16(uint32_t dst, const void* src) {
    asm volatile("cp.async.cg.shared.global [%0], [%1], 16;"
                 :: "r"(dst), "l"(src));
}

__device__ __forceinline__ void ldsm4(uint32_t* r, uint32_t a) {
    asm volatile("ldmatrix.sync.aligned.m8n8.x4.shared.b16 {%0,%1,%2,%3}, [%4];"
                 : "=r"(r[0]), "=r"(r[1]), "=r"(r[2]), "=r"(r[3]) : "r"(a));
}

__device__ __forceinline__ void ldsm2(uint32_t* r, uint32_t a) {
    asm volatile("ldmatrix.sync.aligned.m8n8.x2.shared.b16 {%0,%1}, [%2];"
                 : "=r"(r[0]), "=r"(r[1]) : "r"(a));
}

__device__ __forceinline__ void mma16816(float* c, const uint32_t* a,
                                         const uint32_t* b) {
    asm volatile(
        "mma.sync.aligned.m16n8k16.row.col.f32.bf16.bf16.f32 "
        "{%0,%1,%2,%3}, {%4,%5,%6,%7}, {%8,%9}, {%0,%1,%2,%3};"
        : "+f"(c[0]), "+f"(c[1]), "+f"(c[2]), "+f"(c[3])
        : "r"(a[0]), "r"(a[1]), "r"(a[2]), "r"(a[3]), "r"(b[0]), "r"(b[1]));
}

// ---------------------------------------------------------------------------
// Kernel 1: split x (fp32) -> bf16 hi + bf16 lo
// ---------------------------------------------------------------------------
__global__ void split_x_kernel(const float4* __restrict__ x) {
    long i = (long)blockIdx.x * 256 + threadIdx.x;
    if (i >= NR * KD / 4) return;
    float4 v = x[i];
    __nv_bfloat16 hx = __float2bfloat16(v.x);
    __nv_bfloat16 hy = __float2bfloat16(v.y);
    __nv_bfloat16 hz = __float2bfloat16(v.z);
    __nv_bfloat16 hw = __float2bfloat16(v.w);
    __nv_bfloat162* ph = reinterpret_cast<__nv_bfloat162*>(g_xhi) + 2 * i;
    ph[0] = __halves2bfloat162(hx, hy);
    ph[1] = __halves2bfloat162(hz, hw);
    __nv_bfloat162* pl = reinterpret_cast<__nv_bfloat162*>(g_xlo) + 2 * i;
    pl[0] = __halves2bfloat162(__float2bfloat16(v.x - __bfloat162float(hx)),
                               __float2bfloat16(v.y - __bfloat162float(hy)));
    pl[1] = __halves2bfloat162(__float2bfloat16(v.z - __bfloat162float(hz)),
                               __float2bfloat16(v.w - __bfloat162float(hw)));
}

// ---------------------------------------------------------------------------
// Kernel 2: transpose + split W[K,N] -> whi/wlo [N,K] bf16
// ---------------------------------------------------------------------------
__global__ void splitW_kernel(const float* __restrict__ W) {
    __shared__ float t[32][33];
    int n0 = blockIdx.x * 32, k0 = blockIdx.y * 32;
    int tx = threadIdx.x, ty = threadIdx.y;  // 32 x 8
#pragma unroll
    for (int i = 0; i < 32; i += 8)
        t[ty + i][tx] = W[(long)(k0 + ty + i) * NF + n0 + tx];
    __syncthreads();
#pragma unroll
    for (int i = 0; i < 32; i += 8) {
        float v = t[tx][ty + i];
        long o = (long)(n0 + ty + i) * KD + k0 + tx;
        __nv_bfloat16 h = __float2bfloat16(v);
        g_whi[o] = h;
        g_wlo[o] = __float2bfloat16(v - __bfloat162float(h));
    }
}

// ---------------------------------------------------------------------------
// Kernel 3: HMMA bf16x3 GEMM -> g_feats (fp32)
// D = Ah*Bh + Al*Bh + Ah*Bl over K=2304
// CTA tile 128x128, 8 warps (warp tile 64x32), 3-stage cp.async pipeline.
// ---------------------------------------------------------------------------
struct GemmPtrs {
    const __nv_bfloat16 *Ah, *Al, *Bh, *Bl;
};

__device__ __forceinline__ void load_stage(uint32_t sb, int buf,
                                           const GemmPtrs& g, int k0, int tid) {
    const int r = tid >> 3, j = tid & 7;
    const uint32_t d0 = sb + buf * STAGE + swz((uint32_t)(r * 128 + j * 16));
    const long s0 = (long)r * KD + k0 + j * 8;
#pragma unroll
    for (int i = 0; i < 4; i++) {
        uint32_t d = d0 + i * 4096;         // +32 rows (swizzle invariant)
        long s = s0 + (long)i * 32 * KD;
        cp16(d, g.Ah + s);
        cp16(d + TILE_BYTES, g.Al + s);
        cp16(d + 2 * TILE_BYTES, g.Bh + s);
        cp16(d + 3 * TILE_BYTES, g.Bl + s);
    }
}

__global__ void __launch_bounds__(256, 1) gemm_kernel() {
    extern __shared__ __align__(1024) unsigned char smem_raw[];
    const uint32_t sb = smem_u32(smem_raw);
    const int tid = threadIdx.x, lane = tid & 31, wid = tid >> 5;
    const int nt = blockIdx.x, mt = blockIdx.y;

    GemmPtrs g;
    g.Ah = g_xhi + (long)mt * TM * KD;
    g.Al = g_xlo + (long)mt * TM * KD;
    g.Bh = g_whi + (long)nt * TN * KD;
    g.Bl = g_wlo + (long)nt * TN * KD;

    const int wm = wid & 1, wn = wid >> 1;
    const int m0 = wm * 64, n0 = wn * 32;

    // ldmatrix per-lane row/col-group selectors
    const int arow = (lane & 7) + ((lane >> 3) & 1) * 8;  // 0..15
    const int ajs = lane >> 4;                            // 0,1
    const int brow = lane & 7;
    const int bjs = (lane >> 3) & 1;

    float c[4][4][4];
#pragma unroll
    for (int mi = 0; mi < 4; mi++)
#pragma unroll
        for (int ni = 0; ni < 4; ni++)
#pragma unroll
            for (int q = 0; q < 4; q++) c[mi][ni][q] = 0.f;

    load_stage(sb, 0, g, 0, tid);
    asm volatile("cp.async.commit_group;" ::: "memory");
    load_stage(sb, 1, g, KB, tid);
    asm volatile("cp.async.commit_group;" ::: "memory");

    for (int kb = 0; kb < NKB; kb++) {
        asm volatile("cp.async.wait_group 1;" ::: "memory");
        __syncthreads();
        if (kb + 2 < NKB) {
            int nb = kb + 2;
            load_stage(sb, nb % NSTG, g, nb * KB, tid);
        }
        asm volatile("cp.async.commit_group;" ::: "memory");

        const uint32_t base = sb + (kb % NSTG) * STAGE;
#pragma unroll
        for (int ks = 0; ks < 4; ks++) {
            uint32_t ah[4][4], al[4][4], bh[4][2], bl[4][2];
#pragma unroll
            for (int mi = 0; mi < 4; mi++) {
                uint32_t off = swz((uint32_t)((m0 + mi * 16 + arow) * 128 +
                                              (2 * ks + ajs) * 16));
                ldsm4(ah[mi], base + off);
                ldsm4(al[mi], base + TILE_BYTES + off);
            }
#pragma unroll
            for (int ni = 0; ni < 4; ni++) {
                uint32_t off = swz((uint32_t)((n0 + ni * 8 + brow) * 128 +
                                              (2 * ks + bjs) * 16));
                ldsm2(bh[ni], base + 2 * TILE_BYTES + off);
                ldsm2(bl[ni], base + 3 * TILE_BYTES + off);
            }
#pragma unroll
            for (int mi = 0; mi < 4; mi++)
#pragma unroll
                for (int ni = 0; ni < 4; ni++) {
                    mma16816(c[mi][ni], ah[mi], bh[ni]);
                    mma16816(c[mi][ni], al[mi], bh[ni]);
                    mma16816(c[mi][ni], ah[mi], bl[ni]);
                }
        }
    }

    // Epilogue: fp32 accum -> g_feats
    const int gm = mt * TM + m0, gn = nt * TN + n0;
    const int rr = lane >> 2, cc = (lane & 3) * 2;
#pragma unroll
    for (int mi = 0; mi < 4; mi++)
#pragma unroll
        for (int ni = 0; ni < 4; ni++) {
            long r0 = gm + mi * 16 + rr;
            int col = gn + ni * 8 + cc;
            *reinterpret_cast<float2*>(&g_feats[r0 * NF + col]) =
                make_float2(c[mi][ni][0], c[mi][ni][1]);
            *reinterpret_cast<float2*>(&g_feats[(r0 + 8) * NF + col]) =
                make_float2(c[mi][ni][2], c[mi][ni][3]);
        }
}

// ---------------------------------------------------------------------------
// Kernel 4: activation epilogue  feats -> out
// ---------------------------------------------------------------------------
__global__ void act_kernel(float* __restrict__ out) {
    const float* fr = g_feats + (long)blockIdx.x * NF;
    float* orow = out + (long)blockIdx.x * SOUT;
    for (int c = threadIdx.x; c < SOUT; c += 256) {
        float f = fr[c];
        float gate;
        if (c < 256)       gate = f;                          // silu
        else if (c < 1024) gate = fr[2304 + (c - 256) / 3];   // l=1 gate
        else               gate = fr[2560 + (c - 1024) / 5];  // l=2 gate
        orow[c] = f / (1.0f + __expf(-gate));
    }
}

// ---------------------------------------------------------------------------
extern "C" void kernel_launch(void* const* d_in, const int* in_sizes, int n_in,
                              void* d_out, int out_size) {
    const float* x = (const float*)d_in[0];
    const float* W = (const float*)d_in[1];
    float* out = (float*)d_out;

    split_x_kernel<<<(int)((NR * KD / 4 + 255) / 256), 256>>>((const float4*)x);
    splitW_kernel<<<dim3(NF / 32, KD / 32), dim3(32, 8)>>>(W);

    cudaFuncSetAttribute(gemm_kernel,
                         cudaFuncAttributeMaxDynamicSharedMemorySize,
                         SMEM_BYTES);
    gemm_kernel<<<dim3(NF / TN, (int)(NR / TM)), 256, SMEM_BYTES>>>();

    act_kernel<<<(int)NR, 256>>>(out);
}

// round 5
// speedup vs baseline: 2.6058x; 2.6058x over previous
#include <cuda_runtime.h>
#include <cuda_fp16.h>
#include <cstdint>

// ---------------------------------------------------------------------------
// Problem constants
// ---------------------------------------------------------------------------
static constexpr long NR    = 32768;   // rows of x
static constexpr int  KD    = 2304;    // C_IN
static constexpr int  NF    = 2816;    // C_WITH_GATE
static constexpr int  SOUT  = 2304;    // SIZE_OUT
static constexpr int  NGATE = 512;     // NUM_GATES

static constexpr int TM  = 128;        // CTA tile M
static constexpr int TN  = 128;        // CTA tile N
static constexpr int KB  = 64;         // K per stage
static constexpr int NKB = KD / KB;    // 36

static constexpr int TILE_BYTES = 128 * 128;       // 128x64 fp16 tile = 16KB
static constexpr int STAGE      = 2 * TILE_BYTES;  // A + B = 32KB
static constexpr int NSTG       = 3;
static constexpr int SMEM_BYTES = NSTG * STAGE;    // 98304

// ---------------------------------------------------------------------------
// Scratch (device globals; no runtime allocation)
// ---------------------------------------------------------------------------
__device__ __half g_xh[NR * KD];                // x in fp16
__device__ __half g_wt[(long)NF * KD];          // W^T in fp16: [NF, KD]
__device__ float  g_gates[NR * NGATE];          // sigmoid(gate feats)

// ---------------------------------------------------------------------------
// Helpers (baseline compute_103: cp.async / ldmatrix / mma.sync)
// ---------------------------------------------------------------------------
__device__ __forceinline__ uint32_t smem_u32(const void* p) {
    uint32_t a;
    asm("{ .reg .u64 t; cvta.to.shared.u64 t, %1; cvt.u32.u64 %0, t; }"
        : "=r"(a) : "l"(p));
    return a;
}

__device__ __forceinline__ uint32_t swz(uint32_t o) {
    return o ^ ((o >> 3) & 0x70);   // SW128 (Swizzle<3,4,3>)
}

__device__ __forceinline__ void cp16(uint32_t dst, const void* src) {
    asm volatile("cp.async.cg.shared.global [%0], [%1], 16;"
                 :: "r"(dst), "l"(src));
}

__device__ __forceinline__ void ldsm4(uint32_t* r, uint32_t a) {
    asm volatile("ldmatrix.sync.aligned.m8n8.x4.shared.b16 {%0,%1,%2,%3}, [%4];"
                 : "=r"(r[0]), "=r"(r[1]), "=r"(r[2]), "=r"(r[3]) : "r"(a));
}

__device__ __forceinline__ void ldsm2(uint32_t* r, uint32_t a) {
    asm volatile("ldmatrix.sync.aligned.m8n8.x2.shared.b16 {%0,%1}, [%2];"
                 : "=r"(r[0]), "=r"(r[1]) : "r"(a));
}

__device__ __forceinline__ void mma16816(float* c, const uint32_t* a,
                                         const uint32_t* b) {
    asm volatile(
        "mma.sync.aligned.m16n8k16.row.col.f32.f16.f16.f32 "
        "{%0,%1,%2,%3}, {%4,%5,%6,%7}, {%8,%9}, {%0,%1,%2,%3};"
        : "+f"(c[0]), "+f"(c[1]), "+f"(c[2]), "+f"(c[3])
        : "r"(a[0]), "r"(a[1]), "r"(a[2]), "r"(a[3]), "r"(b[0]), "r"(b[1]));
}

__device__ __forceinline__ float sigf(float v) {
    return 1.0f / (1.0f + __expf(-v));
}

// ---------------------------------------------------------------------------
// Kernel 1: x (fp32) -> fp16
// ---------------------------------------------------------------------------
__global__ void split_x_kernel(const float4* __restrict__ x) {
    long i = (long)blockIdx.x * 256 + threadIdx.x;
    if (i >= NR * KD / 4) return;
    float4 v = x[i];
    __half2* p = reinterpret_cast<__half2*>(g_xh) + 2 * i;
    p[0] = __floats2half2_rn(v.x, v.y);
    p[1] = __floats2half2_rn(v.z, v.w);
}

// ---------------------------------------------------------------------------
// Kernel 2: transpose W[K,NF] -> g_wt [NF,KD] fp16
// ---------------------------------------------------------------------------
__global__ void splitW_kernel(const float* __restrict__ W) {
    __shared__ float t[32][33];
    int n0 = blockIdx.x * 32, k0 = blockIdx.y * 32;
    int tx = threadIdx.x, ty = threadIdx.y;  // 32 x 8
#pragma unroll
    for (int i = 0; i < 32; i += 8)
        t[ty + i][tx] = W[(long)(k0 + ty + i) * NF + n0 + tx];
    __syncthreads();
#pragma unroll
    for (int i = 0; i < 32; i += 8)
        g_wt[(long)(n0 + ty + i) * KD + k0 + tx] = __float2half_rn(t[tx][ty + i]);
}

// ---------------------------------------------------------------------------
// Kernel 3: fp16 HMMA GEMM, fused epilogue.
//   mode 0: n-range = gate cols [SOUT, NF) -> sigmoid -> g_gates
//   mode 1: n-range = field cols [0, SOUT) -> silu / gate-mul -> out
// CTA tile 128x128, 8 warps (64x32 each), 3-stage cp.async pipeline.
// ---------------------------------------------------------------------------
__device__ __forceinline__ void load_stage(uint32_t sb, int buf,
                                           const __half* __restrict__ A,
                                           const __half* __restrict__ B,
                                           int k0, int tid) {
    const int r = tid >> 3, j = tid & 7;
    const uint32_t d0 = sb + buf * STAGE + swz((uint32_t)(r * 128 + j * 16));
    const long s0 = (long)r * KD + k0 + j * 8;
#pragma unroll
    for (int i = 0; i < 4; i++) {
        uint32_t d = d0 + i * 4096;          // +32 rows (swizzle invariant)
        long s = s0 + (long)i * 32 * KD;
        cp16(d, A + s);
        cp16(d + TILE_BYTES, B + s);
    }
}

__global__ void __launch_bounds__(256, 2) gemm_kernel(int n_off, int mode,
                                                      float* __restrict__ out) {
    extern __shared__ __align__(1024) unsigned char smem_raw[];
    const uint32_t sb = smem_u32(smem_raw);
    const int tid = threadIdx.x, lane = tid & 31, wid = tid >> 5;
    const int nt = blockIdx.x, mt = blockIdx.y;

    const __half* A = g_xh + (long)mt * TM * KD;
    const __half* B = g_wt + (long)(n_off + nt * TN) * KD;

    const int wm = wid & 1, wn = wid >> 1;
    const int m0 = wm * 64, n0 = wn * 32;

    const int arow = (lane & 7) + ((lane >> 3) & 1) * 8;  // 0..15
    const int ajs = lane >> 4;                            // 0,1
    const int brow = lane & 7;
    const int bjs = (lane >> 3) & 1;

    float c[4][4][4];
#pragma unroll
    for (int mi = 0; mi < 4; mi++)
#pragma unroll
        for (int ni = 0; ni < 4; ni++)
#pragma unroll
            for (int q = 0; q < 4; q++) c[mi][ni][q] = 0.f;

    load_stage(sb, 0, A, B, 0, tid);
    asm volatile("cp.async.commit_group;" ::: "memory");
    load_stage(sb, 1, A, B, KB, tid);
    asm volatile("cp.async.commit_group;" ::: "memory");

    for (int kb = 0; kb < NKB; kb++) {
        asm volatile("cp.async.wait_group 1;" ::: "memory");
        __syncthreads();
        if (kb + 2 < NKB)
            load_stage(sb, (kb + 2) % NSTG, A, B, (kb + 2) * KB, tid);
        asm volatile("cp.async.commit_group;" ::: "memory");

        const uint32_t base = sb + (kb % NSTG) * STAGE;
#pragma unroll
        for (int ks = 0; ks < 4; ks++) {
            uint32_t a[4][4], b[4][2];
#pragma unroll
            for (int mi = 0; mi < 4; mi++) {
                uint32_t off = swz((uint32_t)((m0 + mi * 16 + arow) * 128 +
                                              (2 * ks + ajs) * 16));
                ldsm4(a[mi], base + off);
            }
#pragma unroll
            for (int ni = 0; ni < 4; ni++) {
                uint32_t off = swz((uint32_t)((n0 + ni * 8 + brow) * 128 +
                                              (2 * ks + bjs) * 16));
                ldsm2(b[ni], base + TILE_BYTES + off);
            }
#pragma unroll
            for (int mi = 0; mi < 4; mi++)
#pragma unroll
                for (int ni = 0; ni < 4; ni++)
                    mma16816(c[mi][ni], a[mi], b[ni]);
        }
    }

    // ----- fused epilogue -----
    const long gm = (long)mt * TM + m0;
    const int rr = lane >> 2, cc = (lane & 3) * 2;

    if (mode == 0) {
        // gate columns -> sigmoid -> g_gates [NR, NGATE]
        const int gn = nt * TN + n0;   // 0..511 within gate block
#pragma unroll
        for (int mi = 0; mi < 4; mi++)
#pragma unroll
            for (int ni = 0; ni < 4; ni++) {
                long r0 = gm + mi * 16 + rr;
                int col = gn + ni * 8 + cc;
                *reinterpret_cast<float2*>(&g_gates[r0 * NGATE + col]) =
                    make_float2(sigf(c[mi][ni][0]), sigf(c[mi][ni][1]));
                *reinterpret_cast<float2*>(&g_gates[(r0 + 8) * NGATE + col]) =
                    make_float2(sigf(c[mi][ni][2]), sigf(c[mi][ni][3]));
            }
    } else {
        // field columns -> silu / gate-mul -> out [NR, SOUT]
        const int gn = nt * TN + n0;   // 0..2303 global output col
#pragma unroll
        for (int mi = 0; mi < 4; mi++)
#pragma unroll
            for (int ni = 0; ni < 4; ni++) {
                int col = gn + ni * 8 + cc;
                // gate indices for col, col+1 (uniform-ish within tile)
                int gi0, gi1;
                if (col < 256)       { gi0 = gi1 = -1; }
                else if (col < 1024) { gi0 = (col - 256) / 3;
                                       gi1 = (col + 1 - 256) / 3; }
                else                 { gi0 = 256 + (col - 1024) / 5;
                                       gi1 = 256 + (col + 1 - 1024) / 5; }
#pragma unroll
                for (int h = 0; h < 2; h++) {
                    long r0 = gm + mi * 16 + rr + h * 8;
                    float f0 = c[mi][ni][2 * h], f1 = c[mi][ni][2 * h + 1];
                    float o0, o1;
                    if (col < 256) {
                        o0 = f0 * sigf(f0);
                        o1 = f1 * sigf(f1);
                    } else {
                        const float* grow = g_gates + r0 * NGATE;
                        o0 = f0 * grow[gi0];
                        o1 = f1 * grow[gi1];
                    }
                    *reinterpret_cast<float2*>(&out[r0 * SOUT + col]) =
                        make_float2(o0, o1);
                }
            }
    }
}

// ---------------------------------------------------------------------------
extern "C" void kernel_launch(void* const* d_in, const int* in_sizes, int n_in,
                              void* d_out, int out_size) {
    const float* x = (const float*)d_in[0];
    const float* W = (const float*)d_in[1];
    float* out = (float*)d_out;

    split_x_kernel<<<(int)((NR * KD / 4 + 255) / 256), 256>>>((const float4*)x);
    splitW_kernel<<<dim3(NF / 32, KD / 32), dim3(32, 8)>>>(W);

    cudaFuncSetAttribute(gemm_kernel,
                         cudaFuncAttributeMaxDynamicSharedMemorySize,
                         SMEM_BYTES);
    // gates first (cols SOUT..NF), then fields fused with gating
    gemm_kernel<<<dim3(NGATE / TN, (int)(NR / TM)), 256, SMEM_BYTES>>>(
        SOUT, 0, out);
    gemm_kernel<<<dim3(SOUT / TN, (int)(NR / TM)), 256, SMEM_BYTES>>>(
        0, 1, out);
}